// round 5
// baseline (speedup 1.0000x reference)
#include <cuda_runtime.h>

// ---------------- problem constants ----------------
namespace {
constexpr int N_MOL  = 131072;
constexpr int E_MOL  = 524288;
constexpr int NG     = 4096;
constexpr int D_MOL  = 6;
constexpr int N_PROT = 100000;
constexpr int E_PROT = 1600000;
constexpr int D_PROT = 20;
constexpr int HD     = 64;
constexpr int NTOT   = N_MOL + N_PROT;     // concatenated node space
constexpr int ETOT   = E_MOL + E_PROT;
constexpr int SCAN_B = (NTOT + 1023) / 1024;  // 226 scan blocks
}

// ---------------- scratch (device globals) ----------------
__device__ __align__(256) float g_mA[N_MOL * HD];
__device__ __align__(256) float g_mB[N_MOL * HD];
__device__ __align__(256) float g_pA[N_PROT * HD];
__device__ __align__(256) float g_pB[N_PROT * HD];
// concatenated CSR-by-dst: nodes [0,N_MOL) = mol, [N_MOL,NTOT) = prot
__device__ int g_cnt[NTOT];
__device__ int g_off[NTOT + 1];
__device__ int g_cur[NTOT];
__device__ int g_esrc[ETOT];
__device__ int g_part[256];
__device__ float g_dinv[N_MOL];
__device__ float g_hs1[N_PROT], g_hd1[N_PROT];
__device__ float g_hs2[N_PROT], g_hd2[N_PROT];
__device__ __align__(256) float g_molf[NG * HD];
__device__ float g_gcnt[NG];
__device__ float g_protf[HD];

// ---------------- helpers ----------------
__device__ __forceinline__ float leaky02(float x) { return x > 0.f ? x : 0.2f * x; }

__device__ __forceinline__ void red4(float* a, float x, float y, float z, float w) {
    asm volatile("red.global.add.v4.f32 [%0], {%1,%2,%3,%4};"
                 :: "l"(a), "f"(x), "f"(y), "f"(z), "f"(w) : "memory");
}

// ---------------- init ----------------
__global__ void k_init() {
    int i = blockIdx.x * blockDim.x + threadIdx.x;  // 262144 threads
    if (i < NG * HD) g_molf[i] = 0.f;
    if (i < NG)      g_gcnt[i] = 0.f;
    if (i < HD)      g_protf[i] = 0.f;
    if (i < NTOT)    g_cnt[i] = 0;
    if (i < N_PROT)  { g_hs2[i] = 0.f; g_hd2[i] = 0.f; }
}

// ---------------- CSR build: hist over both graphs ----------------
__global__ void k_hist(const int* __restrict__ mdst, const int* __restrict__ pdst) {
    int idx = blockIdx.x * blockDim.x + threadIdx.x;
    if (idx < E_MOL) atomicAdd(&g_cnt[mdst[idx]], 1);
    else if (idx < ETOT) atomicAdd(&g_cnt[N_MOL + pdst[idx - E_MOL]], 1);
}

// block scan: 256 threads x 4 = 1024 elems/block
__global__ void k_scan1() {
    __shared__ int wsum[8];
    int t = threadIdx.x;
    int base = blockIdx.x * 1024 + t * 4;
    int v0 = 0, v1 = 0, v2 = 0, v3 = 0;
    if (base + 3 < NTOT) {
        int4 v = *(const int4*)&g_cnt[base];
        v0 = v.x; v1 = v.y; v2 = v.z; v3 = v.w;
    } else {
        if (base + 0 < NTOT) v0 = g_cnt[base + 0];
        if (base + 1 < NTOT) v1 = g_cnt[base + 1];
        if (base + 2 < NTOT) v2 = g_cnt[base + 2];
        if (base + 3 < NTOT) v3 = g_cnt[base + 3];
    }
    int s = v0 + v1 + v2 + v3;
    int lane = t & 31, w = t >> 5;
    int inc = s;
#pragma unroll
    for (int o = 1; o < 32; o <<= 1) {
        int x = __shfl_up_sync(0xffffffffu, inc, o);
        if (lane >= o) inc += x;
    }
    if (lane == 31) wsum[w] = inc;
    __syncthreads();
    int wbase = 0;
    for (int i = 0; i < w; i++) wbase += wsum[i];
    int ex = wbase + inc - s;
    if (base + 0 < NTOT) g_off[base + 0] = ex;
    if (base + 1 < NTOT) g_off[base + 1] = ex + v0;
    if (base + 2 < NTOT) g_off[base + 2] = ex + v0 + v1;
    if (base + 3 < NTOT) g_off[base + 3] = ex + v0 + v1 + v2;
    if (t == 255) g_part[blockIdx.x] = wbase + inc;
}

// scan of block totals (SCAN_B <= 256), in-place exclusive
__global__ void k_scan_tot() {
    __shared__ int ws[8];
    int t = threadIdx.x;                 // 256 threads
    int v = (t < SCAN_B) ? g_part[t] : 0;
    int lane = t & 31, w = t >> 5;
    int inc = v;
#pragma unroll
    for (int o = 1; o < 32; o <<= 1) {
        int x = __shfl_up_sync(0xffffffffu, inc, o);
        if (lane >= o) inc += x;
    }
    if (lane == 31) ws[w] = inc;
    __syncthreads();
    int wbase = 0;
    for (int i = 0; i < w; i++) wbase += ws[i];
    if (t < SCAN_B) g_part[t] = wbase + inc - v;
}

// add partials; also compute dinv for mol nodes
__global__ void k_scan_add() {
    int i = blockIdx.x * blockDim.x + threadIdx.x;
    if (i < NTOT) {
        int o = g_off[i] + g_part[i >> 10];
        g_off[i] = o;
        g_cur[i] = o;
        if (i < N_MOL) g_dinv[i] = rsqrtf((float)(g_cnt[i] + 1));
    }
    if (i == 0) g_off[NTOT] = ETOT;
}

__global__ void k_fill(const int* __restrict__ msrc, const int* __restrict__ mdst,
                       const int* __restrict__ psrc, const int* __restrict__ pdst) {
    int idx = blockIdx.x * blockDim.x + threadIdx.x;
    if (idx < E_MOL) {
        int slot = atomicAdd(&g_cur[mdst[idx]], 1);
        g_esrc[slot] = msrc[idx];
    } else if (idx < ETOT) {
        int e = idx - E_MOL;
        int slot = atomicAdd(&g_cur[N_MOL + pdst[e]], 1);
        g_esrc[slot] = psrc[e];
    }
}

// ---------------- layer-1 matvec (both graphs) + GAT attention epilogue ----------------
__global__ void k_mv1(const float* __restrict__ mx, const float* __restrict__ gw1,
                      const float* __restrict__ px, const float* __restrict__ aw1,
                      const float* __restrict__ as1, const float* __restrict__ ad1) {
    const int lane = threadIdx.x & 31, warp = threadIdx.x >> 5;
    if (blockIdx.x < 1024) {
        float w0[D_MOL], w1[D_MOL];
#pragma unroll
        for (int k = 0; k < D_MOL; ++k) {
            w0[k] = __ldg(&gw1[k * HD + lane]);
            w1[k] = __ldg(&gw1[k * HD + 32 + lane]);
        }
        for (int node = blockIdx.x * 8 + warp; node < N_MOL; node += 1024 * 8) {
            float r0 = (lane < D_MOL) ? mx[(size_t)node * D_MOL + lane] : 0.f;
            float a0 = 0.f, a1 = 0.f;
#pragma unroll
            for (int k = 0; k < D_MOL; ++k) {
                float a = __shfl_sync(0xffffffffu, r0, k);
                a0 = fmaf(a, w0[k], a0);
                a1 = fmaf(a, w1[k], a1);
            }
            g_mA[(size_t)node * HD + lane] = a0;
            g_mA[(size_t)node * HD + 32 + lane] = a1;
        }
    } else {
        float w0[D_PROT], w1[D_PROT];
#pragma unroll
        for (int k = 0; k < D_PROT; ++k) {
            w0[k] = __ldg(&aw1[k * HD + lane]);
            w1[k] = __ldg(&aw1[k * HD + 32 + lane]);
        }
        float s0 = __ldg(&as1[lane]), s1 = __ldg(&as1[32 + lane]);
        float d0 = __ldg(&ad1[lane]), d1 = __ldg(&ad1[32 + lane]);
        for (int node = (blockIdx.x - 1024) * 8 + warp; node < N_PROT; node += 1024 * 8) {
            float r0 = (lane < D_PROT) ? px[(size_t)node * D_PROT + lane] : 0.f;
            float a0 = 0.f, a1 = 0.f;
#pragma unroll
            for (int k = 0; k < D_PROT; ++k) {
                float a = __shfl_sync(0xffffffffu, r0, k);
                a0 = fmaf(a, w0[k], a0);
                a1 = fmaf(a, w1[k], a1);
            }
            g_pA[(size_t)node * HD + lane] = a0;
            g_pA[(size_t)node * HD + 32 + lane] = a1;
            float sp = a0 * s0 + a1 * s1;
            float dp = a0 * d0 + a1 * d1;
#pragma unroll
            for (int o = 16; o; o >>= 1) {
                sp += __shfl_xor_sync(0xffffffffu, sp, o);
                dp += __shfl_xor_sync(0xffffffffu, dp, o);
            }
            if (lane == 0) { g_hs1[node] = sp; g_hd1[node] = dp; }
        }
    }
}

// ---------------- layer-2 matvec (both graphs) + GAT attention epilogue ----------------
__global__ void k_mv2(const float* __restrict__ gw2, const float* __restrict__ aw2,
                      const float* __restrict__ as2, const float* __restrict__ ad2) {
    const int lane = threadIdx.x & 31, warp = threadIdx.x >> 5;
    const int j = ((warp & 1) << 5) | lane;
    if (blockIdx.x < 2048) {
        float w[HD];
#pragma unroll
        for (int k = 0; k < HD; ++k) w[k] = __ldg(&gw2[k * HD + j]);
        for (int node = blockIdx.x * 4 + (warp >> 1); node < N_MOL; node += 2048 * 4) {
            const float* row = &g_mB[(size_t)node * HD];
            float r0 = fmaxf(row[lane], 0.f), r1 = fmaxf(row[lane + 32], 0.f);
            float acc = 0.f;
#pragma unroll
            for (int k = 0; k < HD; ++k) {
                float a = __shfl_sync(0xffffffffu, (k < 32) ? r0 : r1, k & 31);
                acc = fmaf(a, w[k], acc);
            }
            g_mA[(size_t)node * HD + j] = acc;
        }
    } else {
        float w[HD];
#pragma unroll
        for (int k = 0; k < HD; ++k) w[k] = __ldg(&aw2[k * HD + j]);
        float sj = __ldg(&as2[j]), dj = __ldg(&ad2[j]);
        for (int node = (blockIdx.x - 2048) * 4 + (warp >> 1); node < N_PROT; node += 2048 * 4) {
            const float* row = &g_pB[(size_t)node * HD];
            float r0 = row[lane], r1 = row[lane + 32];
            float acc = 0.f;
#pragma unroll
            for (int k = 0; k < HD; ++k) {
                float a = __shfl_sync(0xffffffffu, (k < 32) ? r0 : r1, k & 31);
                acc = fmaf(a, w[k], acc);
            }
            g_pA[(size_t)node * HD + j] = acc;
            float sp = acc * sj, dp = acc * dj;
#pragma unroll
            for (int o = 16; o; o >>= 1) {
                sp += __shfl_xor_sync(0xffffffffu, sp, o);
                dp += __shfl_xor_sync(0xffffffffu, dp, o);
            }
            if (lane == 0) { atomicAdd(&g_hs2[node], sp); atomicAdd(&g_hd2[node], dp); }
        }
    }
}

// ---------------- GCN accumulate (warp per dst node, compact CSR) ----------------
template <bool POOL>
__global__ void k_gcn_acc(const float* __restrict__ h, float* __restrict__ out,
                          const float* __restrict__ bias, const int* __restrict__ batch) {
    int wid = (blockIdx.x * blockDim.x + threadIdx.x) >> 5;
    if (wid >= N_MOL) return;
    int lane = threadIdx.x & 31;
    int half = lane >> 4;
    int c4 = (lane & 15) << 2;
    int beg = g_off[wid], end = g_off[wid + 1];
    float dd = g_dinv[wid];
    float4 acc = {0.f, 0.f, 0.f, 0.f};
    if (half == 0) {
        float cs = dd * dd;
        float4 hv = *(const float4*)&h[(size_t)wid * HD + c4];
        acc.x = cs * hv.x; acc.y = cs * hv.y; acc.z = cs * hv.z; acc.w = cs * hv.w;
    }
    for (int base = beg; base < end; base += 32) {
        int nn = min(32, end - base);
        int s = (lane < nn) ? g_esrc[base + lane] : 0;
        float cf = (lane < nn) ? g_dinv[s] * dd : 0.f;
#pragma unroll 4
        for (int k = 0; k < nn; k += 2) {
            int idx = k + half;
            int sk = __shfl_sync(0xffffffffu, s, idx);
            float ck = __shfl_sync(0xffffffffu, cf, idx);
            if (idx < nn) {
                float4 hv = *(const float4*)&h[(size_t)sk * HD + c4];
                acc.x = fmaf(ck, hv.x, acc.x);
                acc.y = fmaf(ck, hv.y, acc.y);
                acc.z = fmaf(ck, hv.z, acc.z);
                acc.w = fmaf(ck, hv.w, acc.w);
            }
        }
    }
    acc.x += __shfl_xor_sync(0xffffffffu, acc.x, 16);
    acc.y += __shfl_xor_sync(0xffffffffu, acc.y, 16);
    acc.z += __shfl_xor_sync(0xffffffffu, acc.z, 16);
    acc.w += __shfl_xor_sync(0xffffffffu, acc.w, 16);
    if (lane < 16) {
        float4 b4 = *(const float4*)&bias[c4];
        acc.x += b4.x; acc.y += b4.y; acc.z += b4.z; acc.w += b4.w;
        if (POOL) {
            int g = batch[wid];
            red4(&g_molf[(size_t)g * HD + c4], acc.x, acc.y, acc.z, acc.w);
            if (lane == 0) atomicAdd(&g_gcnt[g], 1.f);
        } else {
            *(float4*)&out[(size_t)wid * HD + c4] = acc;
        }
    }
}

// ---------------- GAT accumulate (warp per dst node; single-pass softmax) ----------------
template <bool RELU_OUT>
__global__ void k_gat_acc(const float* __restrict__ h, float* __restrict__ out,
                          const float* __restrict__ bias,
                          const float* __restrict__ hs, const float* __restrict__ hd) {
    int wid = (blockIdx.x * blockDim.x + threadIdx.x) >> 5;
    if (wid >= N_PROT) return;
    int lane = threadIdx.x & 31;
    int half = lane >> 4;
    int c4 = (lane & 15) << 2;
    int beg = g_off[N_MOL + wid], end = g_off[N_MOL + wid + 1];
    float hdv = hd[wid];
    float wself = __expf(leaky02(hs[wid] + hdv));
    float ssum = (lane == 0) ? wself : 0.f;
    float4 acc = {0.f, 0.f, 0.f, 0.f};
    if (half == 0) {
        float4 hv = *(const float4*)&h[(size_t)wid * HD + c4];
        acc.x = wself * hv.x; acc.y = wself * hv.y;
        acc.z = wself * hv.z; acc.w = wself * hv.w;
    }
    for (int base = beg; base < end; base += 32) {
        int nn = min(32, end - base);
        int s = (lane < nn) ? g_esrc[base + lane] : 0;
        float wgt = (lane < nn) ? __expf(leaky02(hs[s] + hdv)) : 0.f;
        ssum += wgt;
#pragma unroll 4
        for (int k = 0; k < nn; k += 2) {
            int idx = k + half;
            int sk = __shfl_sync(0xffffffffu, s, idx);
            float wk = __shfl_sync(0xffffffffu, wgt, idx);
            if (idx < nn) {
                float4 hv = *(const float4*)&h[(size_t)sk * HD + c4];
                acc.x = fmaf(wk, hv.x, acc.x);
                acc.y = fmaf(wk, hv.y, acc.y);
                acc.z = fmaf(wk, hv.z, acc.z);
                acc.w = fmaf(wk, hv.w, acc.w);
            }
        }
    }
    acc.x += __shfl_xor_sync(0xffffffffu, acc.x, 16);
    acc.y += __shfl_xor_sync(0xffffffffu, acc.y, 16);
    acc.z += __shfl_xor_sync(0xffffffffu, acc.z, 16);
    acc.w += __shfl_xor_sync(0xffffffffu, acc.w, 16);
#pragma unroll
    for (int o = 16; o; o >>= 1)
        ssum += __shfl_xor_sync(0xffffffffu, ssum, o);
    if (lane < 16) {
        float inv = 1.f / ssum;
        float4 b4 = *(const float4*)&bias[c4];
        float4 v;
        v.x = fmaf(acc.x, inv, b4.x);
        v.y = fmaf(acc.y, inv, b4.y);
        v.z = fmaf(acc.z, inv, b4.z);
        v.w = fmaf(acc.w, inv, b4.w);
        if (RELU_OUT) {
            v.x = fmaxf(v.x, 0.f); v.y = fmaxf(v.y, 0.f);
            v.z = fmaxf(v.z, 0.f); v.w = fmaxf(v.w, 0.f);
        }
        *(float4*)&out[(size_t)wid * HD + c4] = v;
    }
}

// ---------------- pooling + classifier ----------------
__global__ void k_prot_pool(const float* __restrict__ h) {
    int j = threadIdx.x;  // 64
    float s = 0.f;
    for (int i = blockIdx.x; i < N_PROT; i += gridDim.x)
        s += h[(size_t)i * HD + j];
    atomicAdd(&g_protf[j], s);
}

__global__ void k_cls(const float* __restrict__ w1, const float* __restrict__ b1,
                      const float* __restrict__ w2, const float* __restrict__ b2,
                      float* __restrict__ out) {
    int g = blockIdx.x;
    int j = threadIdx.x;
    __shared__ float fused[2 * HD];
    __shared__ float red[2];
    float cnt = fmaxf(g_gcnt[g], 1.f);
    fused[j] = g_molf[(size_t)g * HD + j] / cnt;
    fused[HD + j] = g_protf[j] * (1.f / (float)N_PROT);
    __syncthreads();
    float z = __ldg(&b1[j]);
#pragma unroll
    for (int k = 0; k < 2 * HD; ++k)
        z = fmaf(fused[k], __ldg(&w1[k * HD + j]), z);
    z = fmaxf(z, 0.f);
    float t = z * __ldg(&w2[j]);
#pragma unroll
    for (int o = 16; o; o >>= 1) t += __shfl_xor_sync(0xffffffffu, t, o);
    if ((j & 31) == 0) red[j >> 5] = t;
    __syncthreads();
    if (j == 0)
        out[g] = 1.f / (1.f + expf(-(red[0] + red[1] + __ldg(&b2[0]))));
}

// ---------------- launch ----------------
extern "C" void kernel_launch(void* const* d_in, const int* in_sizes, int n_in,
                              void* d_out, int out_size) {
    const float* mol_x  = (const float*)d_in[0];
    const int*   mei    = (const int*)  d_in[1];
    const int*   mbatch = (const int*)  d_in[2];
    const float* prot_x = (const float*)d_in[3];
    const int*   pei    = (const int*)  d_in[4];
    const float* gw1 = (const float*)d_in[5];
    const float* gb1 = (const float*)d_in[6];
    const float* gw2 = (const float*)d_in[7];
    const float* gb2 = (const float*)d_in[8];
    const float* aw1 = (const float*)d_in[9];
    const float* as1 = (const float*)d_in[10];
    const float* ad1 = (const float*)d_in[11];
    const float* ab1 = (const float*)d_in[12];
    const float* aw2 = (const float*)d_in[13];
    const float* as2 = (const float*)d_in[14];
    const float* ad2 = (const float*)d_in[15];
    const float* ab2 = (const float*)d_in[16];
    const float* cw1 = (const float*)d_in[17];
    const float* cb1 = (const float*)d_in[18];
    const float* cw2 = (const float*)d_in[19];
    const float* cb2 = (const float*)d_in[20];
    float* out = (float*)d_out;

    float *mA, *mB, *pA, *pB, *hs1, *hd1, *hs2, *hd2;
    cudaGetSymbolAddress((void**)&mA, g_mA);
    cudaGetSymbolAddress((void**)&mB, g_mB);
    cudaGetSymbolAddress((void**)&pA, g_pA);
    cudaGetSymbolAddress((void**)&pB, g_pB);
    cudaGetSymbolAddress((void**)&hs1, g_hs1);
    cudaGetSymbolAddress((void**)&hd1, g_hd1);
    cudaGetSymbolAddress((void**)&hs2, g_hs2);
    cudaGetSymbolAddress((void**)&hd2, g_hd2);

    const int* msrc = mei;
    const int* mdst = mei + E_MOL;
    const int* psrc = pei;
    const int* pdst = pei + E_PROT;

    const int T = 256;
    k_init<<<1024, T>>>();

    // ---- CSR build (both graphs, concatenated node space) ----
    k_hist<<<(ETOT + T - 1) / T, T>>>(mdst, pdst);
    k_scan1<<<SCAN_B, T>>>();
    k_scan_tot<<<1, 256>>>();
    k_scan_add<<<(NTOT + T - 1) / T, T>>>();
    k_fill<<<(ETOT + T - 1) / T, T>>>(msrc, mdst, psrc, pdst);

    // ---- layer 1: matvecs (both graphs) + GAT1 attention scalars ----
    k_mv1<<<2048, T>>>(mol_x, gw1, prot_x, aw1, as1, ad1);
    k_gcn_acc<false><<<(N_MOL + 7) / 8, T>>>(mA, mB, gb1, nullptr);
    k_gat_acc<true><<<(N_PROT + 7) / 8, T>>>(pA, pB, ab1, hs1, hd1);

    // ---- layer 2: matvecs + GAT2 attention scalars ----
    k_mv2<<<4096, T>>>(gw2, aw2, as2, ad2);
    k_gcn_acc<true><<<(N_MOL + 7) / 8, T>>>(mA, nullptr, gb2, mbatch);
    k_gat_acc<false><<<(N_PROT + 7) / 8, T>>>(pA, pB, ab2, hs2, hd2);

    k_prot_pool<<<512, 64>>>(pB);
    k_cls<<<NG, HD>>>(cw1, cb1, cw2, cb2, out);
}

// round 6
// speedup vs baseline: 1.2679x; 1.2679x over previous
#include <cuda_runtime.h>

// ---------------- problem constants ----------------
namespace {
constexpr int N_MOL  = 131072;
constexpr int E_MOL  = 524288;
constexpr int NG     = 4096;
constexpr int D_MOL  = 6;
constexpr int N_PROT = 100000;
constexpr int E_PROT = 1600000;
constexpr int D_PROT = 20;
constexpr int HD     = 64;
}

// ---------------- scratch (device globals; no allocation allowed) ----------------
__device__ __align__(256) float g_mA[N_MOL * HD];
__device__ __align__(256) float g_mB[N_MOL * HD];
__device__ __align__(256) float g_pA[N_PROT * HD];
__device__ __align__(256) float g_pB[N_PROT * HD];
// CSR-by-dst for both graphs
__device__ int g_mcnt[N_MOL];
__device__ int g_moff[N_MOL + 1];
__device__ int g_mcur[N_MOL];
__device__ int g_msrc[E_MOL];
__device__ int g_pcnt[N_PROT];
__device__ int g_poff[N_PROT + 1];
__device__ int g_pcur[N_PROT];
__device__ int g_psrc[E_PROT];
__device__ int g_part[256];          // scan partials
__device__ float g_dinv[N_MOL];
__device__ float g_hs[N_PROT];
__device__ float g_hd[N_PROT];
__device__ __align__(256) float g_molf[NG * HD];
__device__ float g_gcnt[NG];
__device__ float g_protf[HD];

// ---------------- helpers ----------------
__device__ __forceinline__ float leaky02(float x) { return x > 0.f ? x : 0.2f * x; }

__device__ __forceinline__ void red4(float* a, float x, float y, float z, float w) {
    asm volatile("red.global.add.v4.f32 [%0], {%1,%2,%3,%4};"
                 :: "l"(a), "f"(x), "f"(y), "f"(z), "f"(w) : "memory");
}

// ---------------- setup kernels ----------------
__global__ void k_init() {
    int i = blockIdx.x * blockDim.x + threadIdx.x;   // covers 262144
    if (i < NG * HD) g_molf[i] = 0.f;
    if (i < NG)      g_gcnt[i] = 0.f;
    if (i < HD)      g_protf[i] = 0.f;
    if (i < N_MOL)   g_mcnt[i] = 0;
    if (i < N_PROT)  g_pcnt[i] = 0;
}

__global__ void k_hist(const int* __restrict__ dst, int* __restrict__ cnt, int E) {
    int e = blockIdx.x * blockDim.x + threadIdx.x;
    if (e < E) atomicAdd(&cnt[dst[e]], 1);
}

// block scan: 256 threads x 4 elems = 1024 elems/block
__global__ void k_scan1(const int* __restrict__ cnt, int* __restrict__ off,
                        int* __restrict__ part, int n) {
    __shared__ int wsum[8];
    int t = threadIdx.x;
    int base = blockIdx.x * 1024 + t * 4;
    int v0 = 0, v1 = 0, v2 = 0, v3 = 0;
    if (base + 3 < n) {
        int4 v = *(const int4*)&cnt[base];
        v0 = v.x; v1 = v.y; v2 = v.z; v3 = v.w;
    } else {
        if (base + 0 < n) v0 = cnt[base + 0];
        if (base + 1 < n) v1 = cnt[base + 1];
        if (base + 2 < n) v2 = cnt[base + 2];
        if (base + 3 < n) v3 = cnt[base + 3];
    }
    int s = v0 + v1 + v2 + v3;
    int lane = t & 31, w = t >> 5;
    int inc = s;
#pragma unroll
    for (int o = 1; o < 32; o <<= 1) {
        int x = __shfl_up_sync(0xffffffffu, inc, o);
        if (lane >= o) inc += x;
    }
    if (lane == 31) wsum[w] = inc;
    __syncthreads();
    int wbase = 0;
    for (int i = 0; i < w; i++) wbase += wsum[i];
    int ex = wbase + inc - s;
    if (base + 0 < n) off[base + 0] = ex;
    if (base + 1 < n) off[base + 1] = ex + v0;
    if (base + 2 < n) off[base + 2] = ex + v0 + v1;
    if (base + 3 < n) off[base + 3] = ex + v0 + v1 + v2;
    if (t == 255) part[blockIdx.x] = wbase + inc;
}

// scan of block totals (nb <= 128), in-place exclusive
__global__ void k_scan_tot(int* __restrict__ part, int nb) {
    __shared__ int ws[4];
    int t = threadIdx.x;                 // 128 threads
    int v = (t < nb) ? part[t] : 0;
    int lane = t & 31, w = t >> 5;
    int inc = v;
#pragma unroll
    for (int o = 1; o < 32; o <<= 1) {
        int x = __shfl_up_sync(0xffffffffu, inc, o);
        if (lane >= o) inc += x;
    }
    if (lane == 31) ws[w] = inc;
    __syncthreads();
    int wbase = 0;
    for (int i = 0; i < w; i++) wbase += ws[i];
    if (t < nb) part[t] = wbase + inc - v;
}

__global__ void k_scan_add(int* __restrict__ off, const int* __restrict__ part,
                           int* __restrict__ cur, int n, int e_total) {
    int i = blockIdx.x * blockDim.x + threadIdx.x;
    if (i < n) {
        int o = off[i] + part[i >> 10];
        off[i] = o;
        cur[i] = o;
    }
    if (i == 0) off[n] = e_total;
}

__global__ void k_fill(const int* __restrict__ src, const int* __restrict__ dst,
                       int* __restrict__ cur, int* __restrict__ srcs, int E) {
    int e = blockIdx.x * blockDim.x + threadIdx.x;
    if (e < E) {
        int slot = atomicAdd(&cur[dst[e]], 1);
        srcs[slot] = src[e];
    }
}

__global__ void k_dinv() {
    int i = blockIdx.x * blockDim.x + threadIdx.x;
    if (i < N_MOL) g_dinv[i] = rsqrtf((float)(g_mcnt[i] + 1));
}

// ---------------- dense matvec: out[node][j] = sum_k (relu?)in[node][k] * W[k][j] ----------------
template <int DIN, bool RELU_IN>
__global__ void k_matvec(const float* __restrict__ in, const float* __restrict__ W,
                         float* __restrict__ out, int n) {
    const int lane = threadIdx.x & 31;
    const int warp = threadIdx.x >> 5;
    const int j = ((warp & 1) << 5) | lane;
    float wreg[DIN];
#pragma unroll
    for (int k = 0; k < DIN; ++k) wreg[k] = __ldg(&W[k * HD + j]);
    const int step = gridDim.x * 4;
    for (int node = blockIdx.x * 4 + (warp >> 1); node < n; node += step) {
        const float* row = in + (size_t)node * DIN;
        float r0 = 0.f, r1 = 0.f;
        if (DIN >= 32) {
            r0 = row[lane];
            if (DIN > 32 && lane + 32 < DIN) r1 = row[lane + 32];
        } else if (lane < DIN) {
            r0 = row[lane];
        }
        if (RELU_IN) { r0 = fmaxf(r0, 0.f); r1 = fmaxf(r1, 0.f); }
        float acc = 0.f;
#pragma unroll
        for (int k = 0; k < DIN; ++k) {
            float a = __shfl_sync(0xffffffffu, (k < 32) ? r0 : r1, k & 31);
            acc = fmaf(a, wreg[k], acc);
        }
        out[(size_t)node * HD + j] = acc;
    }
}

// ---------------- GCN accumulate (warp per dst node) ----------------
template <bool POOL>
__global__ void k_gcn_acc(const float* __restrict__ h, float* __restrict__ out,
                          const float* __restrict__ bias, const int* __restrict__ batch) {
    int wid = (blockIdx.x * blockDim.x + threadIdx.x) >> 5;
    if (wid >= N_MOL) return;
    int lane = threadIdx.x & 31;
    int half = lane >> 4;
    int c4 = (lane & 15) << 2;
    int beg = g_moff[wid], end = g_moff[wid + 1];
    float dd = g_dinv[wid];
    float4 acc = {0.f, 0.f, 0.f, 0.f};
    if (half == 0) {
        float cs = dd * dd;
        float4 hv = *(const float4*)&h[(size_t)wid * HD + c4];
        acc.x = cs * hv.x; acc.y = cs * hv.y; acc.z = cs * hv.z; acc.w = cs * hv.w;
    }
    for (int base = beg; base < end; base += 32) {
        int nn = min(32, end - base);
        int s = (lane < nn) ? g_msrc[base + lane] : 0;
        float cf = (lane < nn) ? g_dinv[s] * dd : 0.f;
#pragma unroll 4
        for (int k = 0; k < nn; k += 2) {
            int idx = k + half;
            int sk = __shfl_sync(0xffffffffu, s, idx);
            float ck = __shfl_sync(0xffffffffu, cf, idx);
            if (idx < nn) {
                float4 hv = *(const float4*)&h[(size_t)sk * HD + c4];
                acc.x = fmaf(ck, hv.x, acc.x);
                acc.y = fmaf(ck, hv.y, acc.y);
                acc.z = fmaf(ck, hv.z, acc.z);
                acc.w = fmaf(ck, hv.w, acc.w);
            }
        }
    }
    acc.x += __shfl_xor_sync(0xffffffffu, acc.x, 16);
    acc.y += __shfl_xor_sync(0xffffffffu, acc.y, 16);
    acc.z += __shfl_xor_sync(0xffffffffu, acc.z, 16);
    acc.w += __shfl_xor_sync(0xffffffffu, acc.w, 16);
    if (lane < 16) {
        float4 b4 = *(const float4*)&bias[c4];
        acc.x += b4.x; acc.y += b4.y; acc.z += b4.z; acc.w += b4.w;
        if (POOL) {
            int g = batch[wid];
            red4(&g_molf[(size_t)g * HD + c4], acc.x, acc.y, acc.z, acc.w);
            if (lane == 0) atomicAdd(&g_gcnt[g], 1.f);
        } else {
            *(float4*)&out[(size_t)wid * HD + c4] = acc;
        }
    }
}

// ---------------- GAT per-node attention scalars ----------------
__global__ void k_att(const float* __restrict__ h, const float* __restrict__ asrc,
                      const float* __restrict__ adst) {
    int wid = (blockIdx.x * blockDim.x + threadIdx.x) >> 5;
    int lane = threadIdx.x & 31;
    if (wid >= N_PROT) return;
    float h0 = h[(size_t)wid * HD + lane];
    float h1 = h[(size_t)wid * HD + lane + 32];
    float s = h0 * __ldg(&asrc[lane]) + h1 * __ldg(&asrc[lane + 32]);
    float d = h0 * __ldg(&adst[lane]) + h1 * __ldg(&adst[lane + 32]);
#pragma unroll
    for (int o = 16; o; o >>= 1) {
        s += __shfl_xor_sync(0xffffffffu, s, o);
        d += __shfl_xor_sync(0xffffffffu, d, o);
    }
    if (lane == 0) { g_hs[wid] = s; g_hd[wid] = d; }
}

// ---------------- GAT accumulate (warp per dst node; SINGLE-PASS softmax) ----------------
// softmax is shift-invariant; logits here are O(+-2) so exp without max is safe
template <bool RELU_OUT>
__global__ void k_gat_acc(const float* __restrict__ h, float* __restrict__ out,
                          const float* __restrict__ bias) {
    int wid = (blockIdx.x * blockDim.x + threadIdx.x) >> 5;
    if (wid >= N_PROT) return;
    int lane = threadIdx.x & 31;
    int half = lane >> 4;
    int c4 = (lane & 15) << 2;
    int beg = g_poff[wid], end = g_poff[wid + 1];
    float hdv = g_hd[wid];
    float wself = __expf(leaky02(g_hs[wid] + hdv));
    float ssum = (lane == 0) ? wself : 0.f;
    float4 acc = {0.f, 0.f, 0.f, 0.f};
    if (half == 0) {
        float4 hv = *(const float4*)&h[(size_t)wid * HD + c4];
        acc.x = wself * hv.x; acc.y = wself * hv.y;
        acc.z = wself * hv.z; acc.w = wself * hv.w;
    }
    for (int base = beg; base < end; base += 32) {
        int nn = min(32, end - base);
        int s = (lane < nn) ? g_psrc[base + lane] : 0;
        float wgt = (lane < nn) ? __expf(leaky02(g_hs[s] + hdv)) : 0.f;
        ssum += wgt;
#pragma unroll 4
        for (int k = 0; k < nn; k += 2) {
            int idx = k + half;
            int sk = __shfl_sync(0xffffffffu, s, idx);
            float wk = __shfl_sync(0xffffffffu, wgt, idx);
            if (idx < nn) {
                float4 hv = *(const float4*)&h[(size_t)sk * HD + c4];
                acc.x = fmaf(wk, hv.x, acc.x);
                acc.y = fmaf(wk, hv.y, acc.y);
                acc.z = fmaf(wk, hv.z, acc.z);
                acc.w = fmaf(wk, hv.w, acc.w);
            }
        }
    }
    acc.x += __shfl_xor_sync(0xffffffffu, acc.x, 16);
    acc.y += __shfl_xor_sync(0xffffffffu, acc.y, 16);
    acc.z += __shfl_xor_sync(0xffffffffu, acc.z, 16);
    acc.w += __shfl_xor_sync(0xffffffffu, acc.w, 16);
#pragma unroll
    for (int o = 16; o; o >>= 1)
        ssum += __shfl_xor_sync(0xffffffffu, ssum, o);
    if (lane < 16) {
        float inv = 1.f / ssum;
        float4 b4 = *(const float4*)&bias[c4];
        float4 v;
        v.x = fmaf(acc.x, inv, b4.x);
        v.y = fmaf(acc.y, inv, b4.y);
        v.z = fmaf(acc.z, inv, b4.z);
        v.w = fmaf(acc.w, inv, b4.w);
        if (RELU_OUT) {
            v.x = fmaxf(v.x, 0.f); v.y = fmaxf(v.y, 0.f);
            v.z = fmaxf(v.z, 0.f); v.w = fmaxf(v.w, 0.f);
        }
        *(float4*)&out[(size_t)wid * HD + c4] = v;
    }
}

// ---------------- pooling + classifier ----------------
__global__ void k_prot_pool(const float* __restrict__ h) {
    int j = threadIdx.x;  // 64
    float s = 0.f;
    for (int i = blockIdx.x; i < N_PROT; i += gridDim.x)
        s += h[(size_t)i * HD + j];
    atomicAdd(&g_protf[j], s);
}

__global__ void k_cls(const float* __restrict__ w1, const float* __restrict__ b1,
                      const float* __restrict__ w2, const float* __restrict__ b2,
                      float* __restrict__ out) {
    int g = blockIdx.x;
    int j = threadIdx.x;
    __shared__ float fused[2 * HD];
    __shared__ float red[2];
    float cnt = fmaxf(g_gcnt[g], 1.f);
    fused[j] = g_molf[(size_t)g * HD + j] / cnt;
    fused[HD + j] = g_protf[j] * (1.f / (float)N_PROT);
    __syncthreads();
    float z = __ldg(&b1[j]);
#pragma unroll
    for (int k = 0; k < 2 * HD; ++k)
        z = fmaf(fused[k], __ldg(&w1[k * HD + j]), z);
    z = fmaxf(z, 0.f);
    float t = z * __ldg(&w2[j]);
#pragma unroll
    for (int o = 16; o; o >>= 1) t += __shfl_xor_sync(0xffffffffu, t, o);
    if ((j & 31) == 0) red[j >> 5] = t;
    __syncthreads();
    if (j == 0)
        out[g] = 1.f / (1.f + expf(-(red[0] + red[1] + __ldg(&b2[0]))));
}

// ---------------- launch ----------------
extern "C" void kernel_launch(void* const* d_in, const int* in_sizes, int n_in,
                              void* d_out, int out_size) {
    const float* mol_x  = (const float*)d_in[0];
    const int*   mei    = (const int*)  d_in[1];
    const int*   mbatch = (const int*)  d_in[2];
    const float* prot_x = (const float*)d_in[3];
    const int*   pei    = (const int*)  d_in[4];
    const float* gw1 = (const float*)d_in[5];
    const float* gb1 = (const float*)d_in[6];
    const float* gw2 = (const float*)d_in[7];
    const float* gb2 = (const float*)d_in[8];
    const float* aw1 = (const float*)d_in[9];
    const float* as1 = (const float*)d_in[10];
    const float* ad1 = (const float*)d_in[11];
    const float* ab1 = (const float*)d_in[12];
    const float* aw2 = (const float*)d_in[13];
    const float* as2 = (const float*)d_in[14];
    const float* ad2 = (const float*)d_in[15];
    const float* ab2 = (const float*)d_in[16];
    const float* cw1 = (const float*)d_in[17];
    const float* cb1 = (const float*)d_in[18];
    const float* cw2 = (const float*)d_in[19];
    const float* cb2 = (const float*)d_in[20];
    float* out = (float*)d_out;

    float *mA, *mB, *pA, *pB;
    cudaGetSymbolAddress((void**)&mA, g_mA);
    cudaGetSymbolAddress((void**)&mB, g_mB);
    cudaGetSymbolAddress((void**)&pA, g_pA);
    cudaGetSymbolAddress((void**)&pB, g_pB);
    int *mcnt, *moff, *mcur, *msrcs, *pcnt, *poff, *pcur, *psrcs, *part;
    cudaGetSymbolAddress((void**)&mcnt, g_mcnt);
    cudaGetSymbolAddress((void**)&moff, g_moff);
    cudaGetSymbolAddress((void**)&mcur, g_mcur);
    cudaGetSymbolAddress((void**)&msrcs, g_msrc);
    cudaGetSymbolAddress((void**)&pcnt, g_pcnt);
    cudaGetSymbolAddress((void**)&poff, g_poff);
    cudaGetSymbolAddress((void**)&pcur, g_pcur);
    cudaGetSymbolAddress((void**)&psrcs, g_psrc);
    cudaGetSymbolAddress((void**)&part, g_part);

    const int* msrc = mei;
    const int* mdst = mei + E_MOL;
    const int* psrc = pei;
    const int* pdst = pei + E_PROT;

    const int T = 256;
    k_init<<<(NG * HD + T - 1) / T, T>>>();

    // ---- build CSR (mol) ----
    k_hist<<<(E_MOL + T - 1) / T, T>>>(mdst, mcnt, E_MOL);
    k_scan1<<<(N_MOL + 1023) / 1024, 256>>>(mcnt, moff, part, N_MOL);
    k_scan_tot<<<1, 128>>>(part, (N_MOL + 1023) / 1024);
    k_scan_add<<<(N_MOL + T - 1) / T, T>>>(moff, part, mcur, N_MOL, E_MOL);
    k_fill<<<(E_MOL + T - 1) / T, T>>>(msrc, mdst, mcur, msrcs, E_MOL);
    k_dinv<<<(N_MOL + T - 1) / T, T>>>();

    // ---- molecular branch (GCN x2) ----
    k_matvec<D_MOL, false><<<2048, T>>>(mol_x, gw1, mA, N_MOL);
    k_gcn_acc<false><<<(N_MOL + 7) / 8, T>>>(mA, mB, gb1, nullptr);
    k_matvec<HD, true><<<2048, T>>>(mB, gw2, mA, N_MOL);
    k_gcn_acc<true><<<(N_MOL + 7) / 8, T>>>(mA, nullptr, gb2, mbatch);   // fused pool

    // ---- build CSR (prot) ----
    k_hist<<<(E_PROT + T - 1) / T, T>>>(pdst, pcnt, E_PROT);
    k_scan1<<<(N_PROT + 1023) / 1024, 256>>>(pcnt, poff, part, N_PROT);
    k_scan_tot<<<1, 128>>>(part, (N_PROT + 1023) / 1024);
    k_scan_add<<<(N_PROT + T - 1) / T, T>>>(poff, part, pcur, N_PROT, E_PROT);
    k_fill<<<(E_PROT + T - 1) / T, T>>>(psrc, pdst, pcur, psrcs, E_PROT);

    // ---- protein branch (GAT x2) ----
    k_matvec<D_PROT, false><<<2048, T>>>(prot_x, aw1, pA, N_PROT);
    k_att<<<(N_PROT * 32 + T - 1) / T, T>>>(pA, as1, ad1);
    k_gat_acc<true><<<(N_PROT + 7) / 8, T>>>(pA, pB, ab1);

    k_matvec<HD, false><<<2048, T>>>(pB, aw2, pA, N_PROT);
    k_att<<<(N_PROT * 32 + T - 1) / T, T>>>(pA, as2, ad2);
    k_gat_acc<false><<<(N_PROT + 7) / 8, T>>>(pA, pB, ab2);

    k_prot_pool<<<512, 64>>>(pB);

    // ---- classifier ----
    k_cls<<<NG, HD>>>(cw1, cb1, cw2, cb2, out);
}

// round 7
// speedup vs baseline: 1.3448x; 1.0607x over previous
#include <cuda_runtime.h>
#include <cuda_fp16.h>

// ---------------- problem constants ----------------
namespace {
constexpr int N_MOL  = 131072;
constexpr int E_MOL  = 524288;
constexpr int NG     = 4096;
constexpr int D_MOL  = 6;
constexpr int N_PROT = 100000;
constexpr int E_PROT = 1600000;
constexpr int D_PROT = 20;
constexpr int HD     = 64;
}

// ---------------- scratch (device globals; no allocation allowed) ----------------
// gathered feature arrays in fp16 (halves the dominant gather traffic)
__device__ __align__(256) __half g_mA[N_MOL * HD];
__device__ __align__(256) __half g_pA[N_PROT * HD];
// dense-read intermediates stay fp32
__device__ __align__(256) float g_mB[N_MOL * HD];
__device__ __align__(256) float g_pB[N_PROT * HD];
// CSR-by-dst for both graphs
__device__ int g_mcnt[N_MOL];
__device__ int g_moff[N_MOL + 1];
__device__ int g_mcur[N_MOL];
__device__ int g_msrc[E_MOL];
__device__ int g_pcnt[N_PROT];
__device__ int g_poff[N_PROT + 1];
__device__ int g_pcur[N_PROT];
__device__ int g_psrc[E_PROT];
__device__ int g_part[256];          // scan partials
__device__ float g_dinv[N_MOL];
__device__ float g_hs[N_PROT];
__device__ float g_hd[N_PROT];
__device__ __align__(256) float g_molf[NG * HD];
__device__ float g_gcnt[NG];
__device__ float g_protf[HD];

// ---------------- helpers ----------------
__device__ __forceinline__ float leaky02(float x) { return x > 0.f ? x : 0.2f * x; }

__device__ __forceinline__ void red4(float* a, float x, float y, float z, float w) {
    asm volatile("red.global.add.v4.f32 [%0], {%1,%2,%3,%4};"
                 :: "l"(a), "f"(x), "f"(y), "f"(z), "f"(w) : "memory");
}

// load 4 consecutive halfs -> float4 (8B aligned)
__device__ __forceinline__ float4 ldh4(const __half* p) {
    uint2 raw = *(const uint2*)p;
    __half2 h01 = *reinterpret_cast<__half2*>(&raw.x);
    __half2 h23 = *reinterpret_cast<__half2*>(&raw.y);
    float2 f01 = __half22float2(h01);
    float2 f23 = __half22float2(h23);
    return make_float4(f01.x, f01.y, f23.x, f23.y);
}

// ---------------- setup kernels ----------------
__global__ void k_init() {
    int i = blockIdx.x * blockDim.x + threadIdx.x;   // covers 262144
    if (i < NG * HD) g_molf[i] = 0.f;
    if (i < NG)      g_gcnt[i] = 0.f;
    if (i < HD)      g_protf[i] = 0.f;
    if (i < N_MOL)   g_mcnt[i] = 0;
    if (i < N_PROT)  g_pcnt[i] = 0;
}

__global__ void k_hist(const int* __restrict__ dst, int* __restrict__ cnt, int E) {
    int e = blockIdx.x * blockDim.x + threadIdx.x;
    if (e < E) atomicAdd(&cnt[dst[e]], 1);
}

// block scan: 256 threads x 4 elems = 1024 elems/block
__global__ void k_scan1(const int* __restrict__ cnt, int* __restrict__ off,
                        int* __restrict__ part, int n) {
    __shared__ int wsum[8];
    int t = threadIdx.x;
    int base = blockIdx.x * 1024 + t * 4;
    int v0 = 0, v1 = 0, v2 = 0, v3 = 0;
    if (base + 3 < n) {
        int4 v = *(const int4*)&cnt[base];
        v0 = v.x; v1 = v.y; v2 = v.z; v3 = v.w;
    } else {
        if (base + 0 < n) v0 = cnt[base + 0];
        if (base + 1 < n) v1 = cnt[base + 1];
        if (base + 2 < n) v2 = cnt[base + 2];
        if (base + 3 < n) v3 = cnt[base + 3];
    }
    int s = v0 + v1 + v2 + v3;
    int lane = t & 31, w = t >> 5;
    int inc = s;
#pragma unroll
    for (int o = 1; o < 32; o <<= 1) {
        int x = __shfl_up_sync(0xffffffffu, inc, o);
        if (lane >= o) inc += x;
    }
    if (lane == 31) wsum[w] = inc;
    __syncthreads();
    int wbase = 0;
    for (int i = 0; i < w; i++) wbase += wsum[i];
    int ex = wbase + inc - s;
    if (base + 0 < n) off[base + 0] = ex;
    if (base + 1 < n) off[base + 1] = ex + v0;
    if (base + 2 < n) off[base + 2] = ex + v0 + v1;
    if (base + 3 < n) off[base + 3] = ex + v0 + v1 + v2;
    if (t == 255) part[blockIdx.x] = wbase + inc;
}

// scan of block totals (nb <= 128), in-place exclusive
__global__ void k_scan_tot(int* __restrict__ part, int nb) {
    __shared__ int ws[4];
    int t = threadIdx.x;                 // 128 threads
    int v = (t < nb) ? part[t] : 0;
    int lane = t & 31, w = t >> 5;
    int inc = v;
#pragma unroll
    for (int o = 1; o < 32; o <<= 1) {
        int x = __shfl_up_sync(0xffffffffu, inc, o);
        if (lane >= o) inc += x;
    }
    if (lane == 31) ws[w] = inc;
    __syncthreads();
    int wbase = 0;
    for (int i = 0; i < w; i++) wbase += ws[i];
    if (t < nb) part[t] = wbase + inc - v;
}

__global__ void k_scan_add(int* __restrict__ off, const int* __restrict__ part,
                           int* __restrict__ cur, int n, int e_total) {
    int i = blockIdx.x * blockDim.x + threadIdx.x;
    if (i < n) {
        int o = off[i] + part[i >> 10];
        off[i] = o;
        cur[i] = o;
    }
    if (i == 0) off[n] = e_total;
}

__global__ void k_fill(const int* __restrict__ src, const int* __restrict__ dst,
                       int* __restrict__ cur, int* __restrict__ srcs, int E) {
    int e = blockIdx.x * blockDim.x + threadIdx.x;
    if (e < E) {
        int slot = atomicAdd(&cur[dst[e]], 1);
        srcs[slot] = src[e];
    }
}

__global__ void k_dinv() {
    int i = blockIdx.x * blockDim.x + threadIdx.x;
    if (i < N_MOL) g_dinv[i] = rsqrtf((float)(g_mcnt[i] + 1));
}

// ---------------- dense matvec: out[node][j] = sum_k (relu?)in[node][k] * W[k][j] ----------------
// fp32 input, fp16 output (the output is subsequently gathered)
template <int DIN, bool RELU_IN>
__global__ void k_matvec(const float* __restrict__ in, const float* __restrict__ W,
                         __half* __restrict__ out, int n) {
    const int lane = threadIdx.x & 31;
    const int warp = threadIdx.x >> 5;
    const int j = ((warp & 1) << 5) | lane;
    float wreg[DIN];
#pragma unroll
    for (int k = 0; k < DIN; ++k) wreg[k] = __ldg(&W[k * HD + j]);
    const int step = gridDim.x * 4;
    for (int node = blockIdx.x * 4 + (warp >> 1); node < n; node += step) {
        const float* row = in + (size_t)node * DIN;
        float r0 = 0.f, r1 = 0.f;
        if (DIN >= 32) {
            r0 = row[lane];
            if (DIN > 32 && lane + 32 < DIN) r1 = row[lane + 32];
        } else if (lane < DIN) {
            r0 = row[lane];
        }
        if (RELU_IN) { r0 = fmaxf(r0, 0.f); r1 = fmaxf(r1, 0.f); }
        float acc = 0.f;
#pragma unroll
        for (int k = 0; k < DIN; ++k) {
            float a = __shfl_sync(0xffffffffu, (k < 32) ? r0 : r1, k & 31);
            acc = fmaf(a, wreg[k], acc);
        }
        out[(size_t)node * HD + j] = __float2half_rn(acc);
    }
}

// ---------------- GCN accumulate (warp per dst node; fp16 gathers) ----------------
template <bool POOL>
__global__ void k_gcn_acc(const __half* __restrict__ h, float* __restrict__ out,
                          const float* __restrict__ bias, const int* __restrict__ batch) {
    int wid = (blockIdx.x * blockDim.x + threadIdx.x) >> 5;
    if (wid >= N_MOL) return;
    int lane = threadIdx.x & 31;
    int half = lane >> 4;
    int c4 = (lane & 15) << 2;
    int beg = g_moff[wid], end = g_moff[wid + 1];
    float dd = g_dinv[wid];
    float4 acc = {0.f, 0.f, 0.f, 0.f};
    if (half == 0) {
        float cs = dd * dd;
        float4 hv = ldh4(&h[(size_t)wid * HD + c4]);
        acc.x = cs * hv.x; acc.y = cs * hv.y; acc.z = cs * hv.z; acc.w = cs * hv.w;
    }
    for (int base = beg; base < end; base += 32) {
        int nn = min(32, end - base);
        int s = (lane < nn) ? g_msrc[base + lane] : 0;
        float cf = (lane < nn) ? g_dinv[s] * dd : 0.f;
#pragma unroll 4
        for (int k = 0; k < nn; k += 2) {
            int idx = k + half;
            int sk = __shfl_sync(0xffffffffu, s, idx);
            float ck = __shfl_sync(0xffffffffu, cf, idx);
            if (idx < nn) {
                float4 hv = ldh4(&h[(size_t)sk * HD + c4]);
                acc.x = fmaf(ck, hv.x, acc.x);
                acc.y = fmaf(ck, hv.y, acc.y);
                acc.z = fmaf(ck, hv.z, acc.z);
                acc.w = fmaf(ck, hv.w, acc.w);
            }
        }
    }
    acc.x += __shfl_xor_sync(0xffffffffu, acc.x, 16);
    acc.y += __shfl_xor_sync(0xffffffffu, acc.y, 16);
    acc.z += __shfl_xor_sync(0xffffffffu, acc.z, 16);
    acc.w += __shfl_xor_sync(0xffffffffu, acc.w, 16);
    if (lane < 16) {
        float4 b4 = *(const float4*)&bias[c4];
        acc.x += b4.x; acc.y += b4.y; acc.z += b4.z; acc.w += b4.w;
        if (POOL) {
            int g = batch[wid];
            red4(&g_molf[(size_t)g * HD + c4], acc.x, acc.y, acc.z, acc.w);
            if (lane == 0) atomicAdd(&g_gcnt[g], 1.f);
        } else {
            *(float4*)&out[(size_t)wid * HD + c4] = acc;
        }
    }
}

// ---------------- GAT per-node attention scalars (fp16 input) ----------------
__global__ void k_att(const __half* __restrict__ h, const float* __restrict__ asrc,
                      const float* __restrict__ adst) {
    int wid = (blockIdx.x * blockDim.x + threadIdx.x) >> 5;
    int lane = threadIdx.x & 31;
    if (wid >= N_PROT) return;
    float h0 = __half2float(h[(size_t)wid * HD + lane]);
    float h1 = __half2float(h[(size_t)wid * HD + lane + 32]);
    float s = h0 * __ldg(&asrc[lane]) + h1 * __ldg(&asrc[lane + 32]);
    float d = h0 * __ldg(&adst[lane]) + h1 * __ldg(&adst[lane + 32]);
#pragma unroll
    for (int o = 16; o; o >>= 1) {
        s += __shfl_xor_sync(0xffffffffu, s, o);
        d += __shfl_xor_sync(0xffffffffu, d, o);
    }
    if (lane == 0) { g_hs[wid] = s; g_hd[wid] = d; }
}

// ---------------- GAT accumulate (warp per dst node; single-pass softmax; fp16 gathers) ----------------
template <bool RELU_OUT>
__global__ void k_gat_acc(const __half* __restrict__ h, float* __restrict__ out,
                          const float* __restrict__ bias) {
    int wid = (blockIdx.x * blockDim.x + threadIdx.x) >> 5;
    if (wid >= N_PROT) return;
    int lane = threadIdx.x & 31;
    int half = lane >> 4;
    int c4 = (lane & 15) << 2;
    int beg = g_poff[wid], end = g_poff[wid + 1];
    float hdv = g_hd[wid];
    float wself = __expf(leaky02(g_hs[wid] + hdv));
    float ssum = (lane == 0) ? wself : 0.f;
    float4 acc = {0.f, 0.f, 0.f, 0.f};
    if (half == 0) {
        float4 hv = ldh4(&h[(size_t)wid * HD + c4]);
        acc.x = wself * hv.x; acc.y = wself * hv.y;
        acc.z = wself * hv.z; acc.w = wself * hv.w;
    }
    for (int base = beg; base < end; base += 32) {
        int nn = min(32, end - base);
        int s = (lane < nn) ? g_psrc[base + lane] : 0;
        float wgt = (lane < nn) ? __expf(leaky02(g_hs[s] + hdv)) : 0.f;
        ssum += wgt;
#pragma unroll 4
        for (int k = 0; k < nn; k += 2) {
            int idx = k + half;
            int sk = __shfl_sync(0xffffffffu, s, idx);
            float wk = __shfl_sync(0xffffffffu, wgt, idx);
            if (idx < nn) {
                float4 hv = ldh4(&h[(size_t)sk * HD + c4]);
                acc.x = fmaf(wk, hv.x, acc.x);
                acc.y = fmaf(wk, hv.y, acc.y);
                acc.z = fmaf(wk, hv.z, acc.z);
                acc.w = fmaf(wk, hv.w, acc.w);
            }
        }
    }
    acc.x += __shfl_xor_sync(0xffffffffu, acc.x, 16);
    acc.y += __shfl_xor_sync(0xffffffffu, acc.y, 16);
    acc.z += __shfl_xor_sync(0xffffffffu, acc.z, 16);
    acc.w += __shfl_xor_sync(0xffffffffu, acc.w, 16);
#pragma unroll
    for (int o = 16; o; o >>= 1)
        ssum += __shfl_xor_sync(0xffffffffu, ssum, o);
    if (lane < 16) {
        float inv = 1.f / ssum;
        float4 b4 = *(const float4*)&bias[c4];
        float4 v;
        v.x = fmaf(acc.x, inv, b4.x);
        v.y = fmaf(acc.y, inv, b4.y);
        v.z = fmaf(acc.z, inv, b4.z);
        v.w = fmaf(acc.w, inv, b4.w);
        if (RELU_OUT) {
            v.x = fmaxf(v.x, 0.f); v.y = fmaxf(v.y, 0.f);
            v.z = fmaxf(v.z, 0.f); v.w = fmaxf(v.w, 0.f);
        }
        *(float4*)&out[(size_t)wid * HD + c4] = v;
    }
}

// ---------------- pooling + classifier ----------------
__global__ void k_prot_pool(const float* __restrict__ h) {
    int j = threadIdx.x;  // 64
    float s = 0.f;
    for (int i = blockIdx.x; i < N_PROT; i += gridDim.x)
        s += h[(size_t)i * HD + j];
    atomicAdd(&g_protf[j], s);
}

__global__ void k_cls(const float* __restrict__ w1, const float* __restrict__ b1,
                      const float* __restrict__ w2, const float* __restrict__ b2,
                      float* __restrict__ out) {
    int g = blockIdx.x;
    int j = threadIdx.x;
    __shared__ float fused[2 * HD];
    __shared__ float red[2];
    float cnt = fmaxf(g_gcnt[g], 1.f);
    fused[j] = g_molf[(size_t)g * HD + j] / cnt;
    fused[HD + j] = g_protf[j] * (1.f / (float)N_PROT);
    __syncthreads();
    float z = __ldg(&b1[j]);
#pragma unroll
    for (int k = 0; k < 2 * HD; ++k)
        z = fmaf(fused[k], __ldg(&w1[k * HD + j]), z);
    z = fmaxf(z, 0.f);
    float t = z * __ldg(&w2[j]);
#pragma unroll
    for (int o = 16; o; o >>= 1) t += __shfl_xor_sync(0xffffffffu, t, o);
    if ((j & 31) == 0) red[j >> 5] = t;
    __syncthreads();
    if (j == 0)
        out[g] = 1.f / (1.f + expf(-(red[0] + red[1] + __ldg(&b2[0]))));
}

// ---------------- launch ----------------
extern "C" void kernel_launch(void* const* d_in, const int* in_sizes, int n_in,
                              void* d_out, int out_size) {
    const float* mol_x  = (const float*)d_in[0];
    const int*   mei    = (const int*)  d_in[1];
    const int*   mbatch = (const int*)  d_in[2];
    const float* prot_x = (const float*)d_in[3];
    const int*   pei    = (const int*)  d_in[4];
    const float* gw1 = (const float*)d_in[5];
    const float* gb1 = (const float*)d_in[6];
    const float* gw2 = (const float*)d_in[7];
    const float* gb2 = (const float*)d_in[8];
    const float* aw1 = (const float*)d_in[9];
    const float* as1 = (const float*)d_in[10];
    const float* ad1 = (const float*)d_in[11];
    const float* ab1 = (const float*)d_in[12];
    const float* aw2 = (const float*)d_in[13];
    const float* as2 = (const float*)d_in[14];
    const float* ad2 = (const float*)d_in[15];
    const float* ab2 = (const float*)d_in[16];
    const float* cw1 = (const float*)d_in[17];
    const float* cb1 = (const float*)d_in[18];
    const float* cw2 = (const float*)d_in[19];
    const float* cb2 = (const float*)d_in[20];
    float* out = (float*)d_out;

    __half *mA, *pA;
    float *mB, *pB;
    cudaGetSymbolAddress((void**)&mA, g_mA);
    cudaGetSymbolAddress((void**)&mB, g_mB);
    cudaGetSymbolAddress((void**)&pA, g_pA);
    cudaGetSymbolAddress((void**)&pB, g_pB);
    int *mcnt, *moff, *mcur, *msrcs, *pcnt, *poff, *pcur, *psrcs, *part;
    cudaGetSymbolAddress((void**)&mcnt, g_mcnt);
    cudaGetSymbolAddress((void**)&moff, g_moff);
    cudaGetSymbolAddress((void**)&mcur, g_mcur);
    cudaGetSymbolAddress((void**)&msrcs, g_msrc);
    cudaGetSymbolAddress((void**)&pcnt, g_pcnt);
    cudaGetSymbolAddress((void**)&poff, g_poff);
    cudaGetSymbolAddress((void**)&pcur, g_pcur);
    cudaGetSymbolAddress((void**)&psrcs, g_psrc);
    cudaGetSymbolAddress((void**)&part, g_part);

    const int* msrc = mei;
    const int* mdst = mei + E_MOL;
    const int* psrc = pei;
    const int* pdst = pei + E_PROT;

    const int T = 256;
    k_init<<<(NG * HD + T - 1) / T, T>>>();

    // ---- build CSR (mol) ----
    k_hist<<<(E_MOL + T - 1) / T, T>>>(mdst, mcnt, E_MOL);
    k_scan1<<<(N_MOL + 1023) / 1024, 256>>>(mcnt, moff, part, N_MOL);
    k_scan_tot<<<1, 128>>>(part, (N_MOL + 1023) / 1024);
    k_scan_add<<<(N_MOL + T - 1) / T, T>>>(moff, part, mcur, N_MOL, E_MOL);
    k_fill<<<(E_MOL + T - 1) / T, T>>>(msrc, mdst, mcur, msrcs, E_MOL);
    k_dinv<<<(N_MOL + T - 1) / T, T>>>();

    // ---- molecular branch (GCN x2) ----
    k_matvec<D_MOL, false><<<2048, T>>>(mol_x, gw1, mA, N_MOL);
    k_gcn_acc<false><<<(N_MOL + 7) / 8, T>>>(mA, mB, gb1, nullptr);
    k_matvec<HD, true><<<2048, T>>>(mB, gw2, mA, N_MOL);
    k_gcn_acc<true><<<(N_MOL + 7) / 8, T>>>(mA, nullptr, gb2, mbatch);   // fused pool

    // ---- build CSR (prot) ----
    k_hist<<<(E_PROT + T - 1) / T, T>>>(pdst, pcnt, E_PROT);
    k_scan1<<<(N_PROT + 1023) / 1024, 256>>>(pcnt, poff, part, N_PROT);
    k_scan_tot<<<1, 128>>>(part, (N_PROT + 1023) / 1024);
    k_scan_add<<<(N_PROT + T - 1) / T, T>>>(poff, part, pcur, N_PROT, E_PROT);
    k_fill<<<(E_PROT + T - 1) / T, T>>>(psrc, pdst, pcur, psrcs, E_PROT);

    // ---- protein branch (GAT x2) ----
    k_matvec<D_PROT, false><<<2048, T>>>(prot_x, aw1, pA, N_PROT);
    k_att<<<(N_PROT * 32 + T - 1) / T, T>>>(pA, as1, ad1);
    k_gat_acc<true><<<(N_PROT + 7) / 8, T>>>(pA, pB, ab1);

    k_matvec<HD, false><<<2048, T>>>(pB, aw2, pA, N_PROT);
    k_att<<<(N_PROT * 32 + T - 1) / T, T>>>(pA, as2, ad2);
    k_gat_acc<false><<<(N_PROT + 7) / 8, T>>>(pA, pB, ab2);

    k_prot_pool<<<512, 64>>>(pB);

    // ---- classifier ----
    k_cls<<<NG, HD>>>(cw1, cb1, cw2, cb2, out);
}

// round 8
// speedup vs baseline: 1.4335x; 1.0659x over previous
#include <cuda_runtime.h>
#include <cuda_fp16.h>

// ---------------- problem constants ----------------
namespace {
constexpr int N_MOL  = 131072;
constexpr int E_MOL  = 524288;
constexpr int NG     = 4096;
constexpr int D_MOL  = 6;
constexpr int N_PROT = 100000;
constexpr int E_PROT = 1600000;
constexpr int D_PROT = 20;
constexpr int HD     = 64;
}

// ---------------- scratch (device globals; no allocation allowed) ----------------
__device__ __align__(256) __half g_mA[N_MOL * HD];
__device__ __align__(256) __half g_pA[N_PROT * HD];
__device__ __align__(256) float g_mB[N_MOL * HD];
__device__ __align__(256) float g_pB[N_PROT * HD];
// CSR-by-dst for both graphs (separate scan partials: branches run concurrently)
__device__ int g_mcnt[N_MOL];
__device__ int g_moff[N_MOL + 1];
__device__ int g_mcur[N_MOL];
__device__ int g_msrc[E_MOL];
__device__ int g_pcnt[N_PROT];
__device__ int g_poff[N_PROT + 1];
__device__ int g_pcur[N_PROT];
__device__ int g_psrc[E_PROT];
__device__ int g_part[256];
__device__ int g_part2[256];
__device__ float g_dinv[N_MOL];
__device__ float g_hs[N_PROT];
__device__ float g_hd[N_PROT];
__device__ __align__(256) float g_molf[NG * HD];
__device__ float g_gcnt[NG];
__device__ float g_protf[HD];

// ---------------- helpers ----------------
__device__ __forceinline__ float leaky02(float x) { return x > 0.f ? x : 0.2f * x; }

__device__ __forceinline__ void red4(float* a, float x, float y, float z, float w) {
    asm volatile("red.global.add.v4.f32 [%0], {%1,%2,%3,%4};"
                 :: "l"(a), "f"(x), "f"(y), "f"(z), "f"(w) : "memory");
}

__device__ __forceinline__ float4 ldh4(const __half* p) {
    uint2 raw = *(const uint2*)p;
    __half2 h01 = *reinterpret_cast<__half2*>(&raw.x);
    __half2 h23 = *reinterpret_cast<__half2*>(&raw.y);
    float2 f01 = __half22float2(h01);
    float2 f23 = __half22float2(h23);
    return make_float4(f01.x, f01.y, f23.x, f23.y);
}

// ---------------- setup kernels ----------------
__global__ void k_init() {
    int i = blockIdx.x * blockDim.x + threadIdx.x;   // covers 262144
    if (i < NG * HD) g_molf[i] = 0.f;
    if (i < NG)      g_gcnt[i] = 0.f;
    if (i < HD)      g_protf[i] = 0.f;
    if (i < N_MOL)   g_mcnt[i] = 0;
    if (i < N_PROT)  g_pcnt[i] = 0;
}

__global__ void k_hist(const int* __restrict__ dst, int* __restrict__ cnt, int E) {
    int e = blockIdx.x * blockDim.x + threadIdx.x;
    if (e < E) atomicAdd(&cnt[dst[e]], 1);
}

__global__ void k_scan1(const int* __restrict__ cnt, int* __restrict__ off,
                        int* __restrict__ part, int n) {
    __shared__ int wsum[8];
    int t = threadIdx.x;
    int base = blockIdx.x * 1024 + t * 4;
    int v0 = 0, v1 = 0, v2 = 0, v3 = 0;
    if (base + 3 < n) {
        int4 v = *(const int4*)&cnt[base];
        v0 = v.x; v1 = v.y; v2 = v.z; v3 = v.w;
    } else {
        if (base + 0 < n) v0 = cnt[base + 0];
        if (base + 1 < n) v1 = cnt[base + 1];
        if (base + 2 < n) v2 = cnt[base + 2];
        if (base + 3 < n) v3 = cnt[base + 3];
    }
    int s = v0 + v1 + v2 + v3;
    int lane = t & 31, w = t >> 5;
    int inc = s;
#pragma unroll
    for (int o = 1; o < 32; o <<= 1) {
        int x = __shfl_up_sync(0xffffffffu, inc, o);
        if (lane >= o) inc += x;
    }
    if (lane == 31) wsum[w] = inc;
    __syncthreads();
    int wbase = 0;
    for (int i = 0; i < w; i++) wbase += wsum[i];
    int ex = wbase + inc - s;
    if (base + 0 < n) off[base + 0] = ex;
    if (base + 1 < n) off[base + 1] = ex + v0;
    if (base + 2 < n) off[base + 2] = ex + v0 + v1;
    if (base + 3 < n) off[base + 3] = ex + v0 + v1 + v2;
    if (t == 255) part[blockIdx.x] = wbase + inc;
}

__global__ void k_scan_tot(int* __restrict__ part, int nb) {
    __shared__ int ws[4];
    int t = threadIdx.x;                 // 128 threads
    int v = (t < nb) ? part[t] : 0;
    int lane = t & 31, w = t >> 5;
    int inc = v;
#pragma unroll
    for (int o = 1; o < 32; o <<= 1) {
        int x = __shfl_up_sync(0xffffffffu, inc, o);
        if (lane >= o) inc += x;
    }
    if (lane == 31) ws[w] = inc;
    __syncthreads();
    int wbase = 0;
    for (int i = 0; i < w; i++) wbase += ws[i];
    if (t < nb) part[t] = wbase + inc - v;
}

__global__ void k_scan_add(int* __restrict__ off, const int* __restrict__ part,
                           int* __restrict__ cur, int n, int e_total) {
    int i = blockIdx.x * blockDim.x + threadIdx.x;
    if (i < n) {
        int o = off[i] + part[i >> 10];
        off[i] = o;
        cur[i] = o;
    }
    if (i == 0) off[n] = e_total;
}

__global__ void k_fill(const int* __restrict__ src, const int* __restrict__ dst,
                       int* __restrict__ cur, int* __restrict__ srcs, int E) {
    int e = blockIdx.x * blockDim.x + threadIdx.x;
    if (e < E) {
        int slot = atomicAdd(&cur[dst[e]], 1);
        srcs[slot] = src[e];
    }
}

__global__ void k_dinv() {
    int i = blockIdx.x * blockDim.x + threadIdx.x;
    if (i < N_MOL) g_dinv[i] = rsqrtf((float)(g_mcnt[i] + 1));
}

// ---------------- dense matvec (fp32 in, fp16 out) ----------------
template <int DIN, bool RELU_IN>
__global__ void k_matvec(const float* __restrict__ in, const float* __restrict__ W,
                         __half* __restrict__ out, int n) {
    const int lane = threadIdx.x & 31;
    const int warp = threadIdx.x >> 5;
    const int j = ((warp & 1) << 5) | lane;
    float wreg[DIN];
#pragma unroll
    for (int k = 0; k < DIN; ++k) wreg[k] = __ldg(&W[k * HD + j]);
    const int step = gridDim.x * 4;
    for (int node = blockIdx.x * 4 + (warp >> 1); node < n; node += step) {
        const float* row = in + (size_t)node * DIN;
        float r0 = 0.f, r1 = 0.f;
        if (DIN >= 32) {
            r0 = row[lane];
            if (DIN > 32 && lane + 32 < DIN) r1 = row[lane + 32];
        } else if (lane < DIN) {
            r0 = row[lane];
        }
        if (RELU_IN) { r0 = fmaxf(r0, 0.f); r1 = fmaxf(r1, 0.f); }
        float acc = 0.f;
#pragma unroll
        for (int k = 0; k < DIN; ++k) {
            float a = __shfl_sync(0xffffffffu, (k < 32) ? r0 : r1, k & 31);
            acc = fmaf(a, wreg[k], acc);
        }
        out[(size_t)node * HD + j] = __float2half_rn(acc);
    }
}

// ---------------- GCN accumulate (warp per dst node; fp16 gathers) ----------------
template <bool POOL>
__global__ void k_gcn_acc(const __half* __restrict__ h, float* __restrict__ out,
                          const float* __restrict__ bias, const int* __restrict__ batch) {
    int wid = (blockIdx.x * blockDim.x + threadIdx.x) >> 5;
    if (wid >= N_MOL) return;
    int lane = threadIdx.x & 31;
    int half = lane >> 4;
    int c4 = (lane & 15) << 2;
    int beg = g_moff[wid], end = g_moff[wid + 1];
    float dd = g_dinv[wid];
    float4 acc = {0.f, 0.f, 0.f, 0.f};
    if (half == 0) {
        float cs = dd * dd;
        float4 hv = ldh4(&h[(size_t)wid * HD + c4]);
        acc.x = cs * hv.x; acc.y = cs * hv.y; acc.z = cs * hv.z; acc.w = cs * hv.w;
    }
    for (int base = beg; base < end; base += 32) {
        int nn = min(32, end - base);
        int s = (lane < nn) ? g_msrc[base + lane] : 0;
        float cf = (lane < nn) ? g_dinv[s] * dd : 0.f;
#pragma unroll 4
        for (int k = 0; k < nn; k += 2) {
            int idx = k + half;
            int sk = __shfl_sync(0xffffffffu, s, idx);
            float ck = __shfl_sync(0xffffffffu, cf, idx);
            if (idx < nn) {
                float4 hv = ldh4(&h[(size_t)sk * HD + c4]);
                acc.x = fmaf(ck, hv.x, acc.x);
                acc.y = fmaf(ck, hv.y, acc.y);
                acc.z = fmaf(ck, hv.z, acc.z);
                acc.w = fmaf(ck, hv.w, acc.w);
            }
        }
    }
    acc.x += __shfl_xor_sync(0xffffffffu, acc.x, 16);
    acc.y += __shfl_xor_sync(0xffffffffu, acc.y, 16);
    acc.z += __shfl_xor_sync(0xffffffffu, acc.z, 16);
    acc.w += __shfl_xor_sync(0xffffffffu, acc.w, 16);
    if (lane < 16) {
        float4 b4 = *(const float4*)&bias[c4];
        acc.x += b4.x; acc.y += b4.y; acc.z += b4.z; acc.w += b4.w;
        if (POOL) {
            int g = batch[wid];
            red4(&g_molf[(size_t)g * HD + c4], acc.x, acc.y, acc.z, acc.w);
            if (lane == 0) atomicAdd(&g_gcnt[g], 1.f);
        } else {
            *(float4*)&out[(size_t)wid * HD + c4] = acc;
        }
    }
}

// ---------------- GAT per-node attention scalars (fp16 input) ----------------
__global__ void k_att(const __half* __restrict__ h, const float* __restrict__ asrc,
                      const float* __restrict__ adst) {
    int wid = (blockIdx.x * blockDim.x + threadIdx.x) >> 5;
    int lane = threadIdx.x & 31;
    if (wid >= N_PROT) return;
    float h0 = __half2float(h[(size_t)wid * HD + lane]);
    float h1 = __half2float(h[(size_t)wid * HD + lane + 32]);
    float s = h0 * __ldg(&asrc[lane]) + h1 * __ldg(&asrc[lane + 32]);
    float d = h0 * __ldg(&adst[lane]) + h1 * __ldg(&adst[lane + 32]);
#pragma unroll
    for (int o = 16; o; o >>= 1) {
        s += __shfl_xor_sync(0xffffffffu, s, o);
        d += __shfl_xor_sync(0xffffffffu, d, o);
    }
    if (lane == 0) { g_hs[wid] = s; g_hd[wid] = d; }
}

// ---------------- GAT accumulate (warp per dst node; single-pass softmax; fp16) ----------------
template <bool RELU_OUT>
__global__ void k_gat_acc(const __half* __restrict__ h, float* __restrict__ out,
                          const float* __restrict__ bias) {
    int wid = (blockIdx.x * blockDim.x + threadIdx.x) >> 5;
    if (wid >= N_PROT) return;
    int lane = threadIdx.x & 31;
    int half = lane >> 4;
    int c4 = (lane & 15) << 2;
    int beg = g_poff[wid], end = g_poff[wid + 1];
    float hdv = g_hd[wid];
    float wself = __expf(leaky02(g_hs[wid] + hdv));
    float ssum = (lane == 0) ? wself : 0.f;
    float4 acc = {0.f, 0.f, 0.f, 0.f};
    if (half == 0) {
        float4 hv = ldh4(&h[(size_t)wid * HD + c4]);
        acc.x = wself * hv.x; acc.y = wself * hv.y;
        acc.z = wself * hv.z; acc.w = wself * hv.w;
    }
    for (int base = beg; base < end; base += 32) {
        int nn = min(32, end - base);
        int s = (lane < nn) ? g_psrc[base + lane] : 0;
        float wgt = (lane < nn) ? __expf(leaky02(g_hs[s] + hdv)) : 0.f;
        ssum += wgt;
#pragma unroll 4
        for (int k = 0; k < nn; k += 2) {
            int idx = k + half;
            int sk = __shfl_sync(0xffffffffu, s, idx);
            float wk = __shfl_sync(0xffffffffu, wgt, idx);
            if (idx < nn) {
                float4 hv = ldh4(&h[(size_t)sk * HD + c4]);
                acc.x = fmaf(wk, hv.x, acc.x);
                acc.y = fmaf(wk, hv.y, acc.y);
                acc.z = fmaf(wk, hv.z, acc.z);
                acc.w = fmaf(wk, hv.w, acc.w);
            }
        }
    }
    acc.x += __shfl_xor_sync(0xffffffffu, acc.x, 16);
    acc.y += __shfl_xor_sync(0xffffffffu, acc.y, 16);
    acc.z += __shfl_xor_sync(0xffffffffu, acc.z, 16);
    acc.w += __shfl_xor_sync(0xffffffffu, acc.w, 16);
#pragma unroll
    for (int o = 16; o; o >>= 1)
        ssum += __shfl_xor_sync(0xffffffffu, ssum, o);
    if (lane < 16) {
        float inv = 1.f / ssum;
        float4 b4 = *(const float4*)&bias[c4];
        float4 v;
        v.x = fmaf(acc.x, inv, b4.x);
        v.y = fmaf(acc.y, inv, b4.y);
        v.z = fmaf(acc.z, inv, b4.z);
        v.w = fmaf(acc.w, inv, b4.w);
        if (RELU_OUT) {
            v.x = fmaxf(v.x, 0.f); v.y = fmaxf(v.y, 0.f);
            v.z = fmaxf(v.z, 0.f); v.w = fmaxf(v.w, 0.f);
        }
        *(float4*)&out[(size_t)wid * HD + c4] = v;
    }
}

// ---------------- pooling + classifier ----------------
__global__ void k_prot_pool(const float* __restrict__ h) {
    int j = threadIdx.x;  // 64
    float s = 0.f;
    for (int i = blockIdx.x; i < N_PROT; i += gridDim.x)
        s += h[(size_t)i * HD + j];
    atomicAdd(&g_protf[j], s);
}

__global__ void k_cls(const float* __restrict__ w1, const float* __restrict__ b1,
                      const float* __restrict__ w2, const float* __restrict__ b2,
                      float* __restrict__ out) {
    int g = blockIdx.x;
    int j = threadIdx.x;
    __shared__ float fused[2 * HD];
    __shared__ float red[2];
    float cnt = fmaxf(g_gcnt[g], 1.f);
    fused[j] = g_molf[(size_t)g * HD + j] / cnt;
    fused[HD + j] = g_protf[j] * (1.f / (float)N_PROT);
    __syncthreads();
    float z = __ldg(&b1[j]);
#pragma unroll
    for (int k = 0; k < 2 * HD; ++k)
        z = fmaf(fused[k], __ldg(&w1[k * HD + j]), z);
    z = fmaxf(z, 0.f);
    float t = z * __ldg(&w2[j]);
#pragma unroll
    for (int o = 16; o; o >>= 1) t += __shfl_xor_sync(0xffffffffu, t, o);
    if ((j & 31) == 0) red[j >> 5] = t;
    __syncthreads();
    if (j == 0)
        out[g] = 1.f / (1.f + expf(-(red[0] + red[1] + __ldg(&b2[0]))));
}

// ---------------- launch ----------------
extern "C" void kernel_launch(void* const* d_in, const int* in_sizes, int n_in,
                              void* d_out, int out_size) {
    const float* mol_x  = (const float*)d_in[0];
    const int*   mei    = (const int*)  d_in[1];
    const int*   mbatch = (const int*)  d_in[2];
    const float* prot_x = (const float*)d_in[3];
    const int*   pei    = (const int*)  d_in[4];
    const float* gw1 = (const float*)d_in[5];
    const float* gb1 = (const float*)d_in[6];
    const float* gw2 = (const float*)d_in[7];
    const float* gb2 = (const float*)d_in[8];
    const float* aw1 = (const float*)d_in[9];
    const float* as1 = (const float*)d_in[10];
    const float* ad1 = (const float*)d_in[11];
    const float* ab1 = (const float*)d_in[12];
    const float* aw2 = (const float*)d_in[13];
    const float* as2 = (const float*)d_in[14];
    const float* ad2 = (const float*)d_in[15];
    const float* ab2 = (const float*)d_in[16];
    const float* cw1 = (const float*)d_in[17];
    const float* cb1 = (const float*)d_in[18];
    const float* cw2 = (const float*)d_in[19];
    const float* cb2 = (const float*)d_in[20];
    float* out = (float*)d_out;

    __half *mA, *pA;
    float *mB, *pB;
    cudaGetSymbolAddress((void**)&mA, g_mA);
    cudaGetSymbolAddress((void**)&mB, g_mB);
    cudaGetSymbolAddress((void**)&pA, g_pA);
    cudaGetSymbolAddress((void**)&pB, g_pB);
    int *mcnt, *moff, *mcur, *msrcs, *pcnt, *poff, *pcur, *psrcs, *part, *part2;
    cudaGetSymbolAddress((void**)&mcnt, g_mcnt);
    cudaGetSymbolAddress((void**)&moff, g_moff);
    cudaGetSymbolAddress((void**)&mcur, g_mcur);
    cudaGetSymbolAddress((void**)&msrcs, g_msrc);
    cudaGetSymbolAddress((void**)&pcnt, g_pcnt);
    cudaGetSymbolAddress((void**)&poff, g_poff);
    cudaGetSymbolAddress((void**)&pcur, g_pcur);
    cudaGetSymbolAddress((void**)&psrcs, g_psrc);
    cudaGetSymbolAddress((void**)&part, g_part);
    cudaGetSymbolAddress((void**)&part2, g_part2);

    const int* msrc = mei;
    const int* mdst = mei + E_MOL;
    const int* psrc = pei;
    const int* pdst = pei + E_PROT;

    // persistent side stream + fork/join events (created once; no device allocs)
    static cudaStream_t s_prot = nullptr;
    static cudaEvent_t ev_fork = nullptr, ev_join = nullptr;
    if (s_prot == nullptr) {
        cudaStreamCreateWithFlags(&s_prot, cudaStreamNonBlocking);
        cudaEventCreateWithFlags(&ev_fork, cudaEventDisableTiming);
        cudaEventCreateWithFlags(&ev_join, cudaEventDisableTiming);
    }

    const int T = 256;
    k_init<<<(NG * HD + T - 1) / T, T>>>();

    // ---- fork: prot branch on side stream ----
    cudaEventRecord(ev_fork, 0);
    cudaStreamWaitEvent(s_prot, ev_fork, 0);

    // prot CSR build
    k_hist<<<(E_PROT + T - 1) / T, T, 0, s_prot>>>(pdst, pcnt, E_PROT);
    k_scan1<<<(N_PROT + 1023) / 1024, 256, 0, s_prot>>>(pcnt, poff, part2, N_PROT);
    k_scan_tot<<<1, 128, 0, s_prot>>>(part2, (N_PROT + 1023) / 1024);
    k_scan_add<<<(N_PROT + T - 1) / T, T, 0, s_prot>>>(poff, part2, pcur, N_PROT, E_PROT);
    k_fill<<<(E_PROT + T - 1) / T, T, 0, s_prot>>>(psrc, pdst, pcur, psrcs, E_PROT);
    // prot GAT x2
    k_matvec<D_PROT, false><<<2048, T, 0, s_prot>>>(prot_x, aw1, pA, N_PROT);
    k_att<<<(N_PROT * 32 + T - 1) / T, T, 0, s_prot>>>(pA, as1, ad1);
    k_gat_acc<true><<<(N_PROT + 7) / 8, T, 0, s_prot>>>(pA, pB, ab1);
    k_matvec<HD, false><<<2048, T, 0, s_prot>>>(pB, aw2, pA, N_PROT);
    k_att<<<(N_PROT * 32 + T - 1) / T, T, 0, s_prot>>>(pA, as2, ad2);
    k_gat_acc<false><<<(N_PROT + 7) / 8, T, 0, s_prot>>>(pA, pB, ab2);
    k_prot_pool<<<512, 64, 0, s_prot>>>(pB);
    cudaEventRecord(ev_join, s_prot);

    // ---- mol branch on main (capture) stream ----
    k_hist<<<(E_MOL + T - 1) / T, T>>>(mdst, mcnt, E_MOL);
    k_scan1<<<(N_MOL + 1023) / 1024, 256>>>(mcnt, moff, part, N_MOL);
    k_scan_tot<<<1, 128>>>(part, (N_MOL + 1023) / 1024);
    k_scan_add<<<(N_MOL + T - 1) / T, T>>>(moff, part, mcur, N_MOL, E_MOL);
    k_fill<<<(E_MOL + T - 1) / T, T>>>(msrc, mdst, mcur, msrcs, E_MOL);
    k_dinv<<<(N_MOL + T - 1) / T, T>>>();
    k_matvec<D_MOL, false><<<2048, T>>>(mol_x, gw1, mA, N_MOL);
    k_gcn_acc<false><<<(N_MOL + 7) / 8, T>>>(mA, mB, gb1, nullptr);
    k_matvec<HD, true><<<2048, T>>>(mB, gw2, mA, N_MOL);
    k_gcn_acc<true><<<(N_MOL + 7) / 8, T>>>(mA, nullptr, gb2, mbatch);   // fused pool

    // ---- join + classifier ----
    cudaStreamWaitEvent(0, ev_join, 0);
    k_cls<<<NG, HD>>>(cw1, cb1, cw2, cb2, out);
}